// round 17
// baseline (speedup 1.0000x reference)
#include <cuda_runtime.h>
#include <math.h>
#include <stdint.h>

// Problem dims (fixed by the dataset)
#define NN 1000
#define PP 50000
#define ZZ 20
#define LL 10

// Persistent one-warp-per-CTA grid for the sequential CAVI kernel
#define NC 131                 // CTAs (1 warp each, all co-resident)
#define NT 32                  // ONE warp per CTA: no block barriers
#define NV 3                   // float4 groups per lane
#define NCOL (NV * 4)          // 12 columns per lane
#define CHW (NV * 128)         // 384 columns per CTA; 131*384 = 50304 >= 50000
#define NSLOT 5                // ceil(NC/32) poll slots per lane

// GEMM config
#define NCH 8                  // n-chunks for ZtX GEMM
#define NCHN (NN / NCH)        // 125

// Scratch (static device globals; no allocation)
__device__ float g_W[ZZ * PP];                   // 4 MB collapsed loadings
__device__ float g_ZtX[ZZ * PP];                 // 4 MB
__device__ float g_ZtXp[NCH * ZZ * PP];          // 32 MB partials
// Publish slots: {m, tag, S, tag} per CTA, double-buffered by step parity.
// Each 8B half is self-validating (tag rides along) -> no fences, no atomics.
__device__ uint4 g_pub[2][NC];

// ---------------------------------------------------------------------------
// Reset publish tags (runs first in the graph each launch)
// ---------------------------------------------------------------------------
__global__ void reset_kernel() {
    int i = blockIdx.x * blockDim.x + threadIdx.x;
    if (i < 2 * NC) ((uint4*)g_pub)[i] = make_uint4(0u, 0u, 0u, 0u);
}

// ---------------------------------------------------------------------------
// winit: g_W = sum_l mean_w[l]*alpha[l], float4-vectorized
// ---------------------------------------------------------------------------
__global__ void winit_kernel(const float4* __restrict__ mw,
                             const float4* __restrict__ al) {
    int idx = blockIdx.x * blockDim.x + threadIdx.x;
    if (idx >= ZZ * PP / 4) return;
    float4 s = make_float4(0.f, 0.f, 0.f, 0.f);
#pragma unroll
    for (int l = 0; l < LL; l++) {
        float4 m = mw[(size_t)l * (ZZ * PP / 4) + idx];
        float4 a = al[(size_t)l * (ZZ * PP / 4) + idx];
        s.x = fmaf(m.x, a.x, s.x);
        s.y = fmaf(m.y, a.y, s.y);
        s.z = fmaf(m.z, a.z, s.z);
        s.w = fmaf(m.w, a.w, s.w);
    }
    ((float4*)g_W)[idx] = s;
}

// ---------------------------------------------------------------------------
// ZtX GEMM: partials over n-chunks, then reduce.
// ---------------------------------------------------------------------------
__global__ __launch_bounds__(256) void ztx_partial_kernel(
    const float* __restrict__ data, const float* __restrict__ mz) {
    __shared__ float sz[NCHN * ZZ];
    int c = blockIdx.y;
    for (int t = threadIdx.x; t < NCHN * ZZ; t += blockDim.x)
        sz[t] = mz[c * (NCHN * ZZ) + t];
    __syncthreads();

    int g = blockIdx.x * blockDim.x + threadIdx.x;
    if (g >= PP / 4) return;
    int j = g * 4;

    float4 acc[ZZ];
#pragma unroll
    for (int k = 0; k < ZZ; k++) acc[k] = make_float4(0.f, 0.f, 0.f, 0.f);

    const float* dp = data + (size_t)c * NCHN * PP + j;
    for (int nn = 0; nn < NCHN; nn++) {
        float4 d = *(const float4*)(dp + (size_t)nn * PP);
#pragma unroll
        for (int k = 0; k < ZZ; k++) {
            float zv = sz[nn * ZZ + k];
            acc[k].x += d.x * zv;
            acc[k].y += d.y * zv;
            acc[k].z += d.z * zv;
            acc[k].w += d.w * zv;
        }
    }
#pragma unroll
    for (int k = 0; k < ZZ; k++)
        *(float4*)&g_ZtXp[(size_t)c * (ZZ * PP) + k * PP + j] = acc[k];
}

__global__ void ztx_reduce_kernel() {
    int idx = blockIdx.x * blockDim.x + threadIdx.x;
    if (idx >= ZZ * PP) return;
    float s = 0.f;
#pragma unroll
    for (int c = 0; c < NCH; c++) s += g_ZtXp[c * (ZZ * PP) + idx];
    g_ZtX[idx] = s;
}

// ---------------------------------------------------------------------------
// Reduction / publish helpers
// ---------------------------------------------------------------------------
__device__ __forceinline__ unsigned f2ord(float x) {
    unsigned u = __float_as_uint(x);
    return (u & 0x80000000u) ? ~u : (u | 0x80000000u);
}
__device__ __forceinline__ float ord2f(unsigned u) {
    return __uint_as_float((u & 0x80000000u) ? (u ^ 0x80000000u) : ~u);
}
__device__ __forceinline__ float warp_max(float v) {
    unsigned r;
    asm volatile("redux.sync.max.u32 %0, %1, 0xffffffff;"
                 : "=r"(r) : "r"(f2ord(v)));
    return ord2f(r);
}
__device__ __forceinline__ float warp_sum(float v) {
#pragma unroll
    for (int o = 16; o; o >>= 1) v += __shfl_xor_sync(0xffffffffu, v, o);
    return v;
}
// GPU-scope relaxed 128-bit publish/poll (volatile = SYS strength = slow).
__device__ __forceinline__ void pub_store(uint4* p, float m, float S, unsigned tag) {
    asm volatile("st.relaxed.gpu.global.v4.u32 [%0], {%1,%2,%3,%4};"
                 :: "l"(p), "r"(__float_as_uint(m)), "r"(tag),
                    "r"(__float_as_uint(S)), "r"(tag) : "memory");
}
__device__ __forceinline__ uint4 pub_load(const uint4* p) {
    uint4 v;
    asm volatile("ld.relaxed.gpu.global.v4.u32 {%0,%1,%2,%3}, [%4];"
                 : "=r"(v.x), "=r"(v.y), "=r"(v.z), "=r"(v.w) : "l"(p) : "memory");
    return v;
}

// ---------------------------------------------------------------------------
// CAVI kernel: 131 one-warp CTAs, 3 float4 column-groups per lane, per-step
// state in registers, W in per-CTA SMEM (k-prologue/epilogue only).
// Per (k,l) step: vector compute -> redux/shfl partial -> tag-fused 16B
// relaxed.gpu publish -> (stores + deep prefetch overlap) -> poll -> combine.
// ---------------------------------------------------------------------------
__global__ void __launch_bounds__(NT, 1)
cavi_kernel(const float* __restrict__ mzz, const float* __restrict__ mw_in,
            const float* __restrict__ a_in, const float* __restrict__ tau_p,
            const float* __restrict__ tau0, const float* __restrict__ pi,
            float* __restrict__ out_mw, float* __restrict__ out_vw,
            float* __restrict__ out_a) {
    __shared__ float4 sW[ZZ][CHW / 4];   // 30 KB collapsed loadings
    __shared__ float sMzz[ZZ * ZZ];

    const int lane = threadIdx.x;
    const int cta = blockIdx.x;
    const int base = cta * CHW;
    const float tau = __ldg(tau_p);

    for (int t = lane; t < ZZ * ZZ; t += NT) sMzz[t] = __ldg(&mzz[t]);

    // group g: lane's float4 at columns base + g*128 + lane*4 .. +3
    bool act[NV];
    int c4[NV];  // float4 index of lane's group within row
#pragma unroll
    for (int g = 0; g < NV; g++) {
        int colb = base + g * 128 + lane * 4;
        act[g] = colb < PP;          // PP % 4 == 0 -> whole-vector validity
        c4[g] = colb / 4;
    }

    // Load W rows into SMEM (LDG.128, coalesced)
#pragma unroll
    for (int j = 0; j < ZZ; j++)
#pragma unroll
        for (int g = 0; g < NV; g++)
            sW[j][g * 32 + lane] =
                act[g] ? __ldg(&((const float4*)g_W)[(size_t)j * (PP / 4) + c4[g]])
                       : make_float4(0.f, 0.f, 0.f, 0.f);
    __syncwarp();  // sMzz is cross-lane

    // prefetched k-state (k=0) and (k=0,l=0) inputs
    float4 ztx_nxt[NV], pi_nxt[NV], mwn[NV], aln[NV];
#pragma unroll
    for (int g = 0; g < NV; g++) {
        ztx_nxt[g] = act[g] ? __ldg(&((const float4*)g_ZtX)[c4[g]])
                            : make_float4(0.f, 0.f, 0.f, 0.f);
        pi_nxt[g] = act[g] ? __ldg(&((const float4*)pi)[c4[g]])
                           : make_float4(1.f, 1.f, 1.f, 1.f);
        mwn[g] = act[g] ? __ldg(&((const float4*)mw_in)[c4[g]])
                        : make_float4(0.f, 0.f, 0.f, 0.f);
        aln[g] = act[g] ? __ldg(&((const float4*)a_in)[c4[g]])
                        : make_float4(0.f, 0.f, 0.f, 0.f);
    }

    int b = 0;  // global step index (0..199)
    for (int k = 0; k < ZZ; k++) {
        const float Ez = sMzz[k * ZZ + k];
        const float invEz = 1.f / Ez;

        // Prologue: D = ZtX[k] - mzz[k,:] @ W; RtZk = D + Ez*Wk; lp = log(pi)
        float4 D[NV], RtZk[NV], lp[NV];
#pragma unroll
        for (int g = 0; g < NV; g++) {
            float4 dot = make_float4(0.f, 0.f, 0.f, 0.f);
#pragma unroll
            for (int j = 0; j < ZZ; j++) {
                float mj = sMzz[k * ZZ + j];
                float4 w = sW[j][g * 32 + lane];
                dot.x = fmaf(mj, w.x, dot.x);
                dot.y = fmaf(mj, w.y, dot.y);
                dot.z = fmaf(mj, w.z, dot.z);
                dot.w = fmaf(mj, w.w, dot.w);
            }
            float4 wk = sW[k][g * 32 + lane];
            D[g] = make_float4(ztx_nxt[g].x - dot.x, ztx_nxt[g].y - dot.y,
                               ztx_nxt[g].z - dot.z, ztx_nxt[g].w - dot.w);
            RtZk[g] = make_float4(fmaf(Ez, wk.x, D[g].x), fmaf(Ez, wk.y, D[g].y),
                                  fmaf(Ez, wk.z, D[g].z), fmaf(Ez, wk.w, D[g].w));
            lp[g] = make_float4(__logf(pi_nxt[g].x), __logf(pi_nxt[g].y),
                                __logf(pi_nxt[g].z), __logf(pi_nxt[g].w));
        }

        const float s2 = 1.f / (Ez * tau);
        const float l_s2 = __logf(s2);

        for (int l = 0; l < LL; l++, b++) {
            const float t0 = __ldg(&tau0[l * ZZ + k]);
            const float s0inv = 1.f / t0;
            const float s2p = s2 + s0inv;
            const float c0 = 0.5f * (l_s2 - __logf(s2p));
            const float c1 = 0.5f * (s0inv / s2p) * (tau * invEz);
            const float varn = 1.f / (tau * Ez + t0);
            const float tv = tau * varn;

            // consume current step inputs, then immediately issue next-step
            // prefetch (gets the WHOLE step duration of cover)
            float4 mwv[NV], av[NV];
#pragma unroll
            for (int g = 0; g < NV; g++) { mwv[g] = mwn[g]; av[g] = aln[g]; }
            {
                int nl = (l + 1 < LL) ? l + 1 : 0;
                int nk = (l + 1 < LL) ? k : k + 1;
                if (nk < ZZ) {
                    size_t rb = ((size_t)nl * ZZ + nk) * (PP / 4);
#pragma unroll
                    for (int g = 0; g < NV; g++)
                        if (act[g]) {
                            mwn[g] = __ldg(&((const float4*)mw_in)[rb + c4[g]]);
                            aln[g] = __ldg(&((const float4*)a_in)[rb + c4[g]]);
                        }
                }
            }

            // E, s, local max over 12 cols
            float4 E[NV], sv[NV];
            float mloc = -INFINITY;
#pragma unroll
            for (int g = 0; g < NV; g++) {
                if (act[g]) {
                    E[g].x = fmaf(Ez, mwv[g].x * av[g].x, D[g].x);
                    E[g].y = fmaf(Ez, mwv[g].y * av[g].y, D[g].y);
                    E[g].z = fmaf(Ez, mwv[g].z * av[g].z, D[g].z);
                    E[g].w = fmaf(Ez, mwv[g].w * av[g].w, D[g].w);
                    sv[g].x = fmaf(c1 * E[g].x, E[g].x, lp[g].x + c0);
                    sv[g].y = fmaf(c1 * E[g].y, E[g].y, lp[g].y + c0);
                    sv[g].z = fmaf(c1 * E[g].z, E[g].z, lp[g].z + c0);
                    sv[g].w = fmaf(c1 * E[g].w, E[g].w, lp[g].w + c0);
                    mloc = fmaxf(mloc, fmaxf(fmaxf(sv[g].x, sv[g].y),
                                             fmaxf(sv[g].z, sv[g].w)));
                } else {
                    E[g] = make_float4(0.f, 0.f, 0.f, 0.f);
                    sv[g] = make_float4(-INFINITY, -INFINITY, -INFINITY, -INFINITY);
                }
            }
            float m_r = warp_max(mloc);

            float4 ev[NV];
            float ssum = 0.f;
#pragma unroll
            for (int g = 0; g < NV; g++) {
                if (act[g]) {
                    ev[g].x = __expf(sv[g].x - m_r);
                    ev[g].y = __expf(sv[g].y - m_r);
                    ev[g].z = __expf(sv[g].z - m_r);
                    ev[g].w = __expf(sv[g].w - m_r);
                    ssum += (ev[g].x + ev[g].y) + (ev[g].z + ev[g].w);
                } else {
                    ev[g] = make_float4(0.f, 0.f, 0.f, 0.f);
                }
            }
            float S_r = warp_sum(ssum);

            // publish CTA partial immediately (critical path head)
            const unsigned tag = (unsigned)(b + 1);
            uint4* buf = g_pub[b & 1];
            if (lane == 0) pub_store(&buf[cta], m_r, S_r, tag);

            // softmax-independent work during publish/poll latency:
            // mean output stores (STG.128) + next-k ZtX/pi prefetch
            {
                size_t rb = (size_t)(l * ZZ + k) * (PP / 4);
#pragma unroll
                for (int g = 0; g < NV; g++)
                    if (act[g])
                        ((float4*)out_mw)[rb + c4[g]] =
                            make_float4(tv * E[g].x, tv * E[g].y,
                                        tv * E[g].z, tv * E[g].w);
            }
            if (l == 0 && k + 1 < ZZ) {
                size_t rb = (size_t)(k + 1) * (PP / 4);
#pragma unroll
                for (int g = 0; g < NV; g++)
                    if (act[g]) {
                        ztx_nxt[g] = __ldg(&((const float4*)g_ZtX)[rb + c4[g]]);
                        pi_nxt[g] = __ldg(&((const float4*)pi)[rb + c4[g]]);
                    }
            }
            if (cta == 0 && lane == 0) out_vw[l * ZZ + k] = varn;

            // poll all 131 slots until every tag == b+1 (5 per lane);
            // nanosleep backoff only on genuinely-waiting sweeps
            float2 part[NSLOT];
            bool ok;
            do {
                ok = true;
#pragma unroll
                for (int it = 0; it < NSLOT; it++) {
                    int j = lane + it * 32;
                    if (j < NC) {
                        uint4 v = pub_load(&buf[j]);
                        ok &= (v.y == tag) & (v.w == tag);
                        part[it] = make_float2(__uint_as_float(v.x),
                                               __uint_as_float(v.z));
                    } else {
                        part[it] = make_float2(-INFINITY, 0.f);
                    }
                }
                if (!__all_sync(0xffffffffu, ok)) {
                    __nanosleep(32);
                    ok = false;
                }
            } while (!ok);

            // combine the 131 partials (whole warp)
            float M = -INFINITY;
#pragma unroll
            for (int it = 0; it < NSLOT; it++) M = fmaxf(M, part[it].x);
            M = warp_max(M);
            float T = 0.f;
#pragma unroll
            for (int it = 0; it < NSLOT; it++)
                if (part[it].y > 0.f) T += part[it].y * __expf(part[it].x - M);
            T = warp_sum(T);

            const float sc = __expf(m_r - M) / T;

            // alpha out (STG.128) + D update:
            // D = E - Ez*(tv*E)*(ev*sc) = E*(1 - Ez*tv*sc*ev)
            const float ets = Ez * tv * sc;
            {
                size_t rb = (size_t)(l * ZZ + k) * (PP / 4);
#pragma unroll
                for (int g = 0; g < NV; g++)
                    if (act[g]) {
                        float4 an = make_float4(ev[g].x * sc, ev[g].y * sc,
                                                ev[g].z * sc, ev[g].w * sc);
                        ((float4*)out_a)[rb + c4[g]] = an;
                        D[g].x = E[g].x * fmaf(-ets, ev[g].x, 1.f);
                        D[g].y = E[g].y * fmaf(-ets, ev[g].y, 1.f);
                        D[g].z = E[g].z * fmaf(-ets, ev[g].z, 1.f);
                        D[g].w = E[g].w * fmaf(-ets, ev[g].w, 1.f);
                    }
            }
        }

        // epilogue: W[k] = (RtZk - D)/Ez
#pragma unroll
        for (int g = 0; g < NV; g++)
            if (act[g])
                sW[k][g * 32 + lane] =
                    make_float4((RtZk[g].x - D[g].x) * invEz,
                                (RtZk[g].y - D[g].y) * invEz,
                                (RtZk[g].z - D[g].z) * invEz,
                                (RtZk[g].w - D[g].w) * invEz);
    }
}

// ---------------------------------------------------------------------------
// Launch
// ---------------------------------------------------------------------------
extern "C" void kernel_launch(void* const* d_in, const int* in_sizes, int n_in,
                              void* d_out, int out_size) {
    const float* data = (const float*)d_in[0];
    const float* mz = (const float*)d_in[1];
    const float* mzz = (const float*)d_in[2];
    const float* mw = (const float*)d_in[3];
    // d_in[4] = var_w (unused: fully overwritten)
    const float* alpha = (const float*)d_in[5];
    const float* tau = (const float*)d_in[6];
    const float* tau0 = (const float*)d_in[7];
    const float* pi = (const float*)d_in[8];

    float* out = (float*)d_out;
    float* out_mw = out;                              // [L,Z,P]
    float* out_vw = out + (size_t)LL * ZZ * PP;       // [L,Z]
    float* out_a = out_vw + LL * ZZ;                  // [L,Z,P]

    reset_kernel<<<1, 512>>>();
    winit_kernel<<<(ZZ * PP / 4 + 255) / 256, 256>>>((const float4*)mw,
                                                     (const float4*)alpha);

    dim3 g2((PP / 4 + 255) / 256, NCH);
    ztx_partial_kernel<<<g2, 256>>>(data, mz);
    ztx_reduce_kernel<<<(ZZ * PP + 255) / 256, 256>>>();

    cavi_kernel<<<NC, NT>>>(mzz, mw, alpha, tau, tau0, pi,
                            out_mw, out_vw, out_a);
}